// round 3
// baseline (speedup 1.0000x reference)
#include <cuda_runtime.h>
#include <cstdint>

#define B_ROWS 16384
#define IN_DIM 1024
#define H_DIM  2048
#define K_TOP  256
#define NC_DIM 1000

// Scratch (no cudaMalloc allowed): two 128 MiB activation buffers.
__device__ float g_h0[(size_t)B_ROWS * H_DIM];
__device__ float g_h1[(size_t)B_ROWS * H_DIM];

// ---------------- packed f32x2 helpers (Blackwell) ----------------
__device__ __forceinline__ unsigned long long dup2(float x) {
    unsigned long long r; unsigned b = __float_as_uint(x);
    asm("mov.b64 %0, {%1, %2};" : "=l"(r) : "r"(b), "r"(b));
    return r;
}
__device__ __forceinline__ void fma2(unsigned long long& d,
                                     unsigned long long a,
                                     unsigned long long b) {
    asm("fma.rn.f32x2 %0, %1, %2, %0;" : "+l"(d) : "l"(a), "l"(b));
}
__device__ __forceinline__ void unpack2(unsigned long long p, float& lo, float& hi) {
    unsigned l, h;
    asm("mov.b64 {%0, %1}, %2;" : "=r"(l), "=r"(h) : "l"(p));
    lo = __uint_as_float(l); hi = __uint_as_float(h);
}

// ---------------- GEMM: C[m,n] = sum_k A[m,k]*W[n,k] + bias[n] ----------------
// A: [M, Kd] row-major, W: [N, Kd] row-major ("NT" gemm). M always multiple of 128.
// BM=BN=128, BK=16, 256 threads, 8x8 per-thread tile via f32x2.
template<bool BOUND_N>
__global__ __launch_bounds__(256, 2)
void gemm_nt_kernel(const float* __restrict__ A, const float* __restrict__ W,
                    const float* __restrict__ bias, float* __restrict__ C,
                    int N, int Kd)
{
    __shared__ float As[2][16][132];   // [buf][k][m], +4 pad
    __shared__ float Bs[2][16][132];   // [buf][k][n]

    const int tid = threadIdx.x;
    const int tx = tid & 15;           // 16 col groups
    const int ty = tid >> 4;           // 16 row groups
    const int m0 = blockIdx.y * 128;
    const int n0 = blockIdx.x * 128;

    // global-load mapping: 512 float4 slots per tile, 2 per thread
    const int lrow = tid >> 2;         // 0..63
    const int lc4  = tid & 3;          // float4 index within 16-wide K
    const size_t aBase0 = (size_t)(m0 + lrow)      * Kd + lc4 * 4;
    const size_t aBase1 = (size_t)(m0 + lrow + 64) * Kd + lc4 * 4;
    const int bRow0 = n0 + lrow, bRow1 = n0 + lrow + 64;
    const size_t bBase0 = (size_t)bRow0 * Kd + lc4 * 4;
    const size_t bBase1 = (size_t)bRow1 * Kd + lc4 * 4;

    unsigned long long acc[8][4];
    #pragma unroll
    for (int i = 0; i < 8; ++i)
        #pragma unroll
        for (int j = 0; j < 4; ++j) acc[i][j] = 0ULL;

    const int nkt = Kd >> 4;

    // preload tile 0
    float4 ra0 = *(const float4*)(A + aBase0);
    float4 ra1 = *(const float4*)(A + aBase1);
    float4 rb0 = make_float4(0.f, 0.f, 0.f, 0.f), rb1 = rb0;
    if (!BOUND_N || bRow0 < N) rb0 = *(const float4*)(W + bBase0);
    if (!BOUND_N || bRow1 < N) rb1 = *(const float4*)(W + bBase1);

    {
        const int kb = lc4 * 4;
        As[0][kb+0][lrow] = ra0.x; As[0][kb+1][lrow] = ra0.y;
        As[0][kb+2][lrow] = ra0.z; As[0][kb+3][lrow] = ra0.w;
        As[0][kb+0][lrow+64] = ra1.x; As[0][kb+1][lrow+64] = ra1.y;
        As[0][kb+2][lrow+64] = ra1.z; As[0][kb+3][lrow+64] = ra1.w;
        Bs[0][kb+0][lrow] = rb0.x; Bs[0][kb+1][lrow] = rb0.y;
        Bs[0][kb+2][lrow] = rb0.z; Bs[0][kb+3][lrow] = rb0.w;
        Bs[0][kb+0][lrow+64] = rb1.x; Bs[0][kb+1][lrow+64] = rb1.y;
        Bs[0][kb+2][lrow+64] = rb1.z; Bs[0][kb+3][lrow+64] = rb1.w;
    }
    __syncthreads();

    for (int kt = 0; kt < nkt; ++kt) {
        const int cur = kt & 1, nxt = cur ^ 1;
        float4 na0, na1, nb0, nb1;
        const bool more = (kt + 1) < nkt;
        if (more) {
            const size_t koff = (size_t)(kt + 1) * 16;
            na0 = *(const float4*)(A + aBase0 + koff);
            na1 = *(const float4*)(A + aBase1 + koff);
            nb0 = make_float4(0.f, 0.f, 0.f, 0.f); nb1 = nb0;
            if (!BOUND_N || bRow0 < N) nb0 = *(const float4*)(W + bBase0 + koff);
            if (!BOUND_N || bRow1 < N) nb1 = *(const float4*)(W + bBase1 + koff);
        }

        #pragma unroll
        for (int kk = 0; kk < 16; ++kk) {
            const float4 av0 = *(const float4*)&As[cur][kk][ty * 8];
            const float4 av1 = *(const float4*)&As[cur][kk][ty * 8 + 4];
            const ulonglong2 bl = *(const ulonglong2*)&Bs[cur][kk][tx * 8];
            const ulonglong2 bh = *(const ulonglong2*)&Bs[cur][kk][tx * 8 + 4];
            unsigned long long bb0 = bl.x, bb1 = bl.y, bb2 = bh.x, bb3 = bh.y;
            unsigned long long aa[8];
            aa[0] = dup2(av0.x); aa[1] = dup2(av0.y);
            aa[2] = dup2(av0.z); aa[3] = dup2(av0.w);
            aa[4] = dup2(av1.x); aa[5] = dup2(av1.y);
            aa[6] = dup2(av1.z); aa[7] = dup2(av1.w);
            #pragma unroll
            for (int i = 0; i < 8; ++i) {
                fma2(acc[i][0], aa[i], bb0);
                fma2(acc[i][1], aa[i], bb1);
                fma2(acc[i][2], aa[i], bb2);
                fma2(acc[i][3], aa[i], bb3);
            }
        }

        if (more) {
            const int kb = lc4 * 4;
            As[nxt][kb+0][lrow] = na0.x; As[nxt][kb+1][lrow] = na0.y;
            As[nxt][kb+2][lrow] = na0.z; As[nxt][kb+3][lrow] = na0.w;
            As[nxt][kb+0][lrow+64] = na1.x; As[nxt][kb+1][lrow+64] = na1.y;
            As[nxt][kb+2][lrow+64] = na1.z; As[nxt][kb+3][lrow+64] = na1.w;
            Bs[nxt][kb+0][lrow] = nb0.x; Bs[nxt][kb+1][lrow] = nb0.y;
            Bs[nxt][kb+2][lrow] = nb0.z; Bs[nxt][kb+3][lrow] = nb0.w;
            Bs[nxt][kb+0][lrow+64] = nb1.x; Bs[nxt][kb+1][lrow+64] = nb1.y;
            Bs[nxt][kb+2][lrow+64] = nb1.z; Bs[nxt][kb+3][lrow+64] = nb1.w;
        }
        __syncthreads();
    }

    // epilogue: unpack, add bias, store
    #pragma unroll
    for (int i = 0; i < 8; ++i) {
        const int m = m0 + ty * 8 + i;
        float* crow = C + (size_t)m * N;
        #pragma unroll
        for (int j = 0; j < 4; ++j) {
            float lo, hi;
            unpack2(acc[i][j], lo, hi);
            const int n = n0 + tx * 8 + j * 2;
            if (!BOUND_N || n < N)     crow[n]     = lo + bias[n];
            if (!BOUND_N || n + 1 < N) crow[n + 1] = hi + bias[n + 1];
        }
    }
}

// ---------------- per-row top-K mask + ReLU (in place) ----------------
// Row length H_DIM=2048, 256 threads, 8 contiguous elems/thread.
// Exact jax.lax.top_k semantics: K largest kept; ties at the K-th value
// broken by lowest index first. Then relu.
__global__ __launch_bounds__(256)
void topk_relu_kernel(float* __restrict__ buf)
{
    __shared__ unsigned s_hist[256];
    __shared__ unsigned s_scan[2][256];
    __shared__ unsigned s_bin, s_k;

    const int tid = threadIdx.x;
    const size_t base = (size_t)blockIdx.x * H_DIM;

    float v[8]; unsigned u[8];
    {
        const float4 f0 = *(const float4*)(buf + base + tid * 8);
        const float4 f1 = *(const float4*)(buf + base + tid * 8 + 4);
        v[0]=f0.x; v[1]=f0.y; v[2]=f0.z; v[3]=f0.w;
        v[4]=f1.x; v[5]=f1.y; v[6]=f1.z; v[7]=f1.w;
    }
    #pragma unroll
    for (int s = 0; s < 8; ++s) {
        const unsigned bits = __float_as_uint(v[s]);
        // order-preserving map: larger float -> larger unsigned
        u[s] = bits ^ ((bits & 0x80000000u) ? 0xFFFFFFFFu : 0x80000000u);
    }

    unsigned prefHi = 0;
    unsigned kneed = K_TOP;

    #pragma unroll
    for (int level = 3; level >= 0; --level) {
        s_hist[tid] = 0;
        __syncthreads();
        #pragma unroll
        for (int s = 0; s < 8; ++s) {
            const unsigned hiBits = (level == 3) ? 0u : (u[s] >> ((level + 1) * 8));
            if (level == 3 || hiBits == prefHi)
                atomicAdd(&s_hist[(u[s] >> (level * 8)) & 255u], 1u);
        }
        __syncthreads();
        // inclusive suffix-sum over 256 bins (descending value order)
        unsigned val = s_hist[tid];
        s_scan[0][tid] = val;
        __syncthreads();
        int src = 0;
        #pragma unroll
        for (int d = 1; d < 256; d <<= 1) {
            if (tid + d < 256) val += s_scan[src][tid + d];
            s_scan[src ^ 1][tid] = val;
            __syncthreads();
            src ^= 1;
        }
        const unsigned above = (tid < 255) ? s_scan[src][tid + 1] : 0u;
        if (val >= kneed && above < kneed) { s_bin = (unsigned)tid; s_k = kneed - above; }
        __syncthreads();
        prefHi = (prefHi << 8) | s_bin;
        kneed = s_k;
        __syncthreads();
    }

    const unsigned T = prefHi;   // key of the K-th largest value
    const unsigned r = kneed;    // # of elements equal to T to keep (lowest index first)

    // exclusive prefix (ascending index) of per-thread equal counts
    unsigned myEq = 0;
    #pragma unroll
    for (int s = 0; s < 8; ++s) myEq += (u[s] == T) ? 1u : 0u;
    unsigned pval = myEq;
    s_scan[0][tid] = pval;
    __syncthreads();
    int src = 0;
    #pragma unroll
    for (int d = 1; d < 256; d <<= 1) {
        if (tid >= d) pval += s_scan[src][tid - d];
        s_scan[src ^ 1][tid] = pval;
        __syncthreads();
        src ^= 1;
    }
    unsigned rank = pval - myEq;   // equals strictly before my chunk

    float o[8];
    #pragma unroll
    for (int s = 0; s < 8; ++s) {
        bool keep;
        if (u[s] > T)       keep = true;
        else if (u[s] == T) { keep = (rank < r); ++rank; }
        else                keep = false;
        o[s] = keep ? fmaxf(v[s], 0.0f) : 0.0f;
    }
    *(float4*)(buf + base + tid * 8)     = make_float4(o[0], o[1], o[2], o[3]);
    *(float4*)(buf + base + tid * 8 + 4) = make_float4(o[4], o[5], o[6], o[7]);
}

// ---------------- launch ----------------
extern "C" void kernel_launch(void* const* d_in, const int* in_sizes, int n_in,
                              void* d_out, int out_size)
{
    const float* x  = (const float*)d_in[0];
    const float* W0 = (const float*)d_in[1];
    const float* b0 = (const float*)d_in[2];
    const float* W1 = (const float*)d_in[3];
    const float* b1 = (const float*)d_in[4];
    const float* Wc = (const float*)d_in[5];
    const float* bc = (const float*)d_in[6];
    float* out = (float*)d_out;

    float *h0 = nullptr, *h1 = nullptr;
    cudaGetSymbolAddress((void**)&h0, g_h0);
    cudaGetSymbolAddress((void**)&h1, g_h1);

    const dim3 blk(256);
    // Layer 0: [B, IN] x [H, IN]^T -> h0
    gemm_nt_kernel<false><<<dim3(H_DIM / 128, B_ROWS / 128), blk>>>(x, W0, b0, h0, H_DIM, IN_DIM);
    topk_relu_kernel<<<B_ROWS, blk>>>(h0);
    // Layer 1: [B, H] x [H, H]^T -> h1
    gemm_nt_kernel<false><<<dim3(H_DIM / 128, B_ROWS / 128), blk>>>(h0, W1, b1, h1, H_DIM, H_DIM);
    topk_relu_kernel<<<B_ROWS, blk>>>(h1);
    // Classifier: [B, H] x [NC, H]^T -> out (N=1000 needs bounds)
    gemm_nt_kernel<true><<<dim3((NC_DIM + 127) / 128, B_ROWS / 128), blk>>>(h1, Wc, bc, out, NC_DIM, H_DIM);
}